// round 6
// baseline (speedup 1.0000x reference)
#include <cuda_runtime.h>

// Problem constants (B=4, N_obj=8 -> 32 objects, N_v=2048 points, 64 anchors, 16-NN)
#define N_V        2048
#define N_OBJS     32
#define ANCHORS    64
#define KNN        16
#define FPS_THREADS 256
#define PPT        8            // points per thread in FPS (2048/256)
#define FULL       0xffffffffu

__device__ int g_anchors[N_OBJS * ANCHORS];

// ---------------------------------------------------------------------------
// Kernel 1: farthest point sampling, one block (256 thr) per object.
// Points staged in SMEM (float4); each thread owns 8 points in registers,
// argmax fused into the min-update loop. Winner lane (ballot+ffs) writes
// its packed (value, inverted-index) partial directly — no shfl on the
// critical path. One barrier per iteration via double-buffered partials.
// Distance arithmetic identical to the R2 kernel that verified at 4.7e-8.
// ---------------------------------------------------------------------------
__global__ __launch_bounds__(FPS_THREADS) void fps_kernel(const float* __restrict__ pos) {
    const int o = blockIdx.x;
    const float* __restrict__ P = pos + (size_t)o * N_V * 3;

    __shared__ float spts[N_V * 3];                       // 24 KB
    __shared__ unsigned long long swk[2][FPS_THREADS / 32];

    const int tid  = threadIdx.x;
    const int lane = tid & 31;
    const int wid  = tid >> 5;

    // vectorized stage: 6144 floats = 1536 float4
    {
        const float4* __restrict__ P4 = (const float4*)P;
        float4* S4 = (float4*)spts;
        for (int i = tid; i < (N_V * 3) / 4; i += FPS_THREADS) S4[i] = P4[i];
    }
    __syncthreads();

    float px[PPT], py[PPT], pz[PPT], md[PPT];
    const float x0 = spts[0], y0 = spts[1], z0 = spts[2];
    float bv = -1.0f;
    int   bi = tid;
#pragma unroll
    for (int k = 0; k < PPT; k++) {
        const int j = tid + FPS_THREADS * k;
        px[k] = spts[j * 3 + 0];
        py[k] = spts[j * 3 + 1];
        pz[k] = spts[j * 3 + 2];
        const float dx = px[k] - x0, dy = py[k] - y0, dz = pz[k] - z0;
        md[k] = dx * dx + dy * dy + dz * dz;              // matches reference FPS formula
        if (md[k] > bv) { bv = md[k]; bi = j; }           // first max -> lowest index
    }
    if (tid == 0) g_anchors[o * ANCHORS + 0] = 0;

    int buf = 0;
    for (int it = 1; it < ANCHORS; ++it) {
        // warp argmax: md >= 0 so raw float bits are monotonic as unsigned.
        // ballot+ffs guarantees exactly ONE writer even on value ties.
        const unsigned u   = __float_as_uint(bv);
        const unsigned m   = __reduce_max_sync(FULL, u);
        const unsigned bal = __ballot_sync(FULL, u == m);
        const int src = __ffs(bal) - 1;
        if (lane == src)                                  // winner writes directly
            swk[buf][wid] = ((unsigned long long)m << 32) | (unsigned)(0x7FFFFFFF - bi);
        __syncthreads();

        // every thread reduces the 8 warp partials (no second barrier)
        unsigned long long best = swk[buf][0];
#pragma unroll
        for (int w = 1; w < FPS_THREADS / 32; w++) {
            const unsigned long long c = swk[buf][w];
            if (c > best) best = c;
        }
        const int bidx = 0x7FFFFFFF - (int)(unsigned)(best & 0xFFFFFFFFull);
        if (tid == 0) g_anchors[o * ANCHORS + it] = bidx;

        const float qx = spts[bidx * 3 + 0];
        const float qy = spts[bidx * 3 + 1];
        const float qz = spts[bidx * 3 + 2];
        bv = -1.0f; bi = tid;
#pragma unroll
        for (int k = 0; k < PPT; k++) {
            const float dx = px[k] - qx, dy = py[k] - qy, dz = pz[k] - qz;
            const float d = dx * dx + dy * dy + dz * dz;
            md[k] = fminf(md[k], d);
            if (md[k] > bv) { bv = md[k]; bi = tid + FPS_THREADS * k; }  // fused argmax
        }
        buf ^= 1;
    }
}

// ---------------------------------------------------------------------------
// Kernel 2: KNN at anchors + gather + output assembly.
// One BLOCK (4 warps) per anchor; each lane owns exactly 16 points.
// Selection is a pure min/max MERGE NETWORK (exact on multisets, no
// redux/ballot/serial chain):
//   1. lane bitonic-sorts its 16 distances ascending
//   2. 5 xor-rounds: keep smallest-16 of (mine, partner) via half-cleaner
//      c[i] = min(v[i], partner_v[15-i]), then 4-stage bitonic re-merge
//   3. lane 0 of each warp spills its sorted run; one barrier
//   4. every warp merges the 4 runs (2 more xor-rounds) -> T = v[15]
//   5. accumulate positions with d <= T
// Distance arithmetic bit-identical to the R2 kernel (4.7e-8).
// ---------------------------------------------------------------------------
__global__ __launch_bounds__(128) void knn_kernel(const float* __restrict__ pos,
                                                  const float* __restrict__ vel,
                                                  const float* __restrict__ phys,
                                                  const float* __restrict__ refp,
                                                  float* __restrict__ out) {
    __shared__ float dsh[KNN][128];                       // unsorted distance park (8 KB)
    __shared__ float cand[4 * 17];                        // 4 sorted runs, stride 17
    __shared__ float psum[4][3];

    const int a    = blockIdx.x;                 // global anchor id [0, 2048)
    const int tid  = threadIdx.x;
    const int lane = tid & 31;
    const int wid  = tid >> 5;
    const int obj  = a >> 6;
    const int aidx = g_anchors[a];

    const float* __restrict__ P = pos + (size_t)obj * N_V * 3;
    const float qx = P[aidx * 3 + 0];
    const float qy = P[aidx * 3 + 1];
    const float qz = P[aidx * 3 + 2];
    const float sqq = qx * qx + qy * qy + qz * qz;

    const int base = wid << 9;                   // this warp's 512-point chunk

    // ---- distances for my 16 points (expression identical to R2) ----
    float v[KNN];
#pragma unroll 4
    for (int k = 0; k < KNN; k++) {
        const int j = base + (k << 5) + lane;
        const float x = P[j * 3 + 0], y = P[j * 3 + 1], z = P[j * 3 + 2];
        float d = (x * x + y * y + z * z + sqq) - 2.0f * (x * qx + y * qy + z * qz);
        if (j == aidx) d += 1e10f;               // reference's diagonal exclusion
        v[k] = d;
        dsh[k][tid] = d;
    }

    // ---- bitonic sort of the 16 values (ascending), value-only ----
#pragma unroll
    for (int kk = 2; kk <= KNN; kk <<= 1) {
#pragma unroll
        for (int jj = kk >> 1; jj > 0; jj >>= 1) {
#pragma unroll
            for (int i = 0; i < KNN; i++) {
                const int l = i ^ jj;
                if (l > i) {
                    const float va = v[i], vb = v[l];
                    const float lo = fminf(va, vb), hi = fmaxf(va, vb);
                    const bool up = ((i & kk) == 0);
                    v[i] = up ? lo : hi;
                    v[l] = up ? hi : lo;
                }
            }
        }
    }

    // ---- warp merge network: 5 xor-rounds keep-smallest-16 ----
#pragma unroll
    for (int m = 1; m <= 16; m <<= 1) {
        float c[KNN];
#pragma unroll
        for (int i = 0; i < KNN; i++)            // half-cleaner vs partner's reversed run
            c[i] = fminf(v[i], __shfl_xor_sync(FULL, v[KNN - 1 - i], m));
#pragma unroll
        for (int jj = 8; jj >= 1; jj >>= 1) {    // bitonic re-merge (c is bitonic)
#pragma unroll
            for (int i = 0; i < KNN; i++) {
                if ((i & jj) == 0) {
                    const int l = i | jj;
                    const float lo = fminf(c[i], c[l]);
                    const float hi = fmaxf(c[i], c[l]);
                    c[i] = lo; c[l] = hi;
                }
            }
        }
#pragma unroll
        for (int i = 0; i < KNN; i++) v[i] = c[i];
    }

    // every lane now holds the warp's sorted top-16; lane 0 spills it
    if (lane == 0) {
#pragma unroll
        for (int i = 0; i < KNN; i++) cand[wid * 17 + i] = v[i];
    }
    __syncthreads();

    // ---- final: every warp merges the 4 runs (2 xor-rounds) -> T ----
    const int L = lane & 3;
    float w2[KNN];
#pragma unroll
    for (int i = 0; i < KNN; i++) w2[i] = cand[L * 17 + i];
#pragma unroll
    for (int m = 1; m <= 2; m <<= 1) {
        float c[KNN];
#pragma unroll
        for (int i = 0; i < KNN; i++)
            c[i] = fminf(w2[i], __shfl_xor_sync(FULL, w2[KNN - 1 - i], m));
#pragma unroll
        for (int jj = 8; jj >= 1; jj >>= 1) {
#pragma unroll
            for (int i = 0; i < KNN; i++) {
                if ((i & jj) == 0) {
                    const int l = i | jj;
                    const float lo = fminf(c[i], c[l]);
                    const float hi = fmaxf(c[i], c[l]);
                    c[i] = lo; c[l] = hi;
                }
            }
        }
#pragma unroll
        for (int i = 0; i < KNN; i++) w2[i] = c[i];
    }
    const float T = w2[KNN - 1];                 // exact 16th-smallest of all 2048

    // ---- accumulate positions of the 16 selected points ----
    float sx = 0.f, sy = 0.f, sz = 0.f;
#pragma unroll 4
    for (int k = 0; k < KNN; k++) {
        if (dsh[k][tid] <= T) {
            const int j = base + (k << 5) + lane;
            sx += P[j * 3 + 0];
            sy += P[j * 3 + 1];
            sz += P[j * 3 + 2];
        }
    }
#pragma unroll
    for (int off = 16; off; off >>= 1) {
        sx += __shfl_xor_sync(FULL, sx, off);
        sy += __shfl_xor_sync(FULL, sy, off);
        sz += __shfl_xor_sync(FULL, sz, off);
    }
    if (lane == 0) { psum[wid][0] = sx; psum[wid][1] = sy; psum[wid][2] = sz; }
    __syncthreads();

    if (tid == 0) {
        const float nx = psum[0][0] + psum[1][0] + psum[2][0] + psum[3][0];
        const float ny = psum[0][1] + psum[1][1] + psum[2][1] + psum[3][1];
        const float nz = psum[0][2] + psum[1][2] + psum[2][2] + psum[3][2];
        float* __restrict__ o = out + (size_t)a * 12;
        const float inv = 1.0f / 16.0f;
        // anchor_dist: mean(neigh) - p
        o[0] = nx * inv - qx;
        o[1] = ny * inv - qy;
        o[2] = nz * inv - qz;
        // anchor_vel
        const float* __restrict__ V = vel + (size_t)obj * N_V * 3;
        o[3] = V[aidx * 3 + 0];
        o[4] = V[aidx * 3 + 1];
        o[5] = V[aidx * 3 + 2];
        // anchor_rel = pos - ref
        const float* __restrict__ R = refp + (size_t)obj * N_V * 3;
        o[6] = qx - R[aidx * 3 + 0];
        o[7] = qy - R[aidx * 3 + 1];
        o[8] = qz - R[aidx * 3 + 2];
        // physics broadcast
        o[9]  = phys[obj * 3 + 0];
        o[10] = phys[obj * 3 + 1];
        o[11] = phys[obj * 3 + 2];
    }
}

extern "C" void kernel_launch(void* const* d_in, const int* in_sizes, int n_in,
                              void* d_out, int out_size) {
    const float* positions  = (const float*)d_in[0];
    const float* velocities = (const float*)d_in[1];
    const float* physics    = (const float*)d_in[2];
    const float* refpos     = (const float*)d_in[3];
    float* out = (float*)d_out;

    fps_kernel<<<N_OBJS, FPS_THREADS>>>(positions);
    knn_kernel<<<N_OBJS * ANCHORS, 128>>>(positions, velocities, physics, refpos, out);
}

// round 7
// speedup vs baseline: 1.0982x; 1.0982x over previous
#include <cuda_runtime.h>

// Problem constants (B=4, N_obj=8 -> 32 objects, N_v=2048 points, 64 anchors, 16-NN)
#define N_V        2048
#define N_OBJS     32
#define ANCHORS    64
#define KNN        16
#define FPS_THREADS 256
#define PPT        8            // points per thread in FPS (2048/256)
#define FULL       0xffffffffu

__device__ int g_anchors[N_OBJS * ANCHORS];

// ---------------------------------------------------------------------------
// Kernel 1: farthest point sampling, one block per object.
// (byte-exact the R1/R2 version — the fastest measured fps configuration)
// ---------------------------------------------------------------------------
__global__ __launch_bounds__(FPS_THREADS) void fps_kernel(const float* __restrict__ pos) {
    const int o = blockIdx.x;
    const float* __restrict__ P = pos + (size_t)o * N_V * 3;

    __shared__ float spts[N_V * 3];                       // 24 KB
    __shared__ unsigned long long swk[2][FPS_THREADS / 32];

    const int tid  = threadIdx.x;
    const int lane = tid & 31;
    const int wid  = tid >> 5;

    for (int i = tid; i < N_V * 3; i += FPS_THREADS) spts[i] = P[i];
    __syncthreads();

    float px[PPT], py[PPT], pz[PPT], md[PPT];
    const float x0 = spts[0], y0 = spts[1], z0 = spts[2];
#pragma unroll
    for (int k = 0; k < PPT; k++) {
        const int j = tid + FPS_THREADS * k;
        px[k] = spts[j * 3 + 0];
        py[k] = spts[j * 3 + 1];
        pz[k] = spts[j * 3 + 2];
        const float dx = px[k] - x0, dy = py[k] - y0, dz = pz[k] - z0;
        md[k] = dx * dx + dy * dy + dz * dz;              // matches reference FPS formula
    }
    if (tid == 0) g_anchors[o * ANCHORS + 0] = 0;

    int buf = 0;
    for (int it = 1; it < ANCHORS; ++it) {
        // local argmax over my 8 points
        float bv = md[0];
        int   bi = tid;
#pragma unroll
        for (int k = 1; k < PPT; k++) {
            if (md[k] > bv) { bv = md[k]; bi = tid + FPS_THREADS * k; }
        }
        // warp argmax: md >= 0 so raw float bits are monotonic as unsigned
        const unsigned u = __float_as_uint(bv);
        const unsigned m = __reduce_max_sync(FULL, u);
        const unsigned bal = __ballot_sync(FULL, u == m);
        const int src = __ffs(bal) - 1;
        const int ci  = __shfl_sync(FULL, bi, src);
        if (lane == 0)
            swk[buf][wid] = ((unsigned long long)m << 32) | (unsigned)(0x7FFFFFFF - ci);
        __syncthreads();

        // every thread reduces the 8 warp partials (no second barrier needed)
        unsigned long long best = swk[buf][0];
#pragma unroll
        for (int w = 1; w < FPS_THREADS / 32; w++) {
            const unsigned long long c = swk[buf][w];
            if (c > best) best = c;
        }
        const int bidx = 0x7FFFFFFF - (int)(unsigned)(best & 0xFFFFFFFFull);
        if (tid == 0) g_anchors[o * ANCHORS + it] = bidx;

        const float qx = spts[bidx * 3 + 0];
        const float qy = spts[bidx * 3 + 1];
        const float qz = spts[bidx * 3 + 2];
#pragma unroll
        for (int k = 0; k < PPT; k++) {
            const float dx = px[k] - qx, dy = py[k] - qy, dz = pz[k] - qz;
            const float d = dx * dx + dy * dy + dz * dz;
            md[k] = fminf(md[k], d);
        }
        buf ^= 1;
    }
}

// ---------------------------------------------------------------------------
// Kernel 2: KNN at anchors + gather + output assembly.
// One BLOCK (4 warps) per anchor; each lane owns exactly 16 points.
// Selection = pure min/max merge network (exact on multisets):
//   1. lane bitonic-sorts its 16 distances ascending (register-resident)
//   2. 5 xor-rounds of IN-PLACE half-cleaner keep-smallest-16 + bitonic
//      re-merge (no second register array -> no spills)
//   3. lane 0 of each warp spills its sorted run; one barrier
//   4. every warp merges the 4 runs: round m=1 full, round m=2 half-cleaner
//      + max-tree only -> T = exact 16th smallest of all 2048
//   5. accumulate positions with d <= T (pristine copy d[16] in registers)
// launch_bounds(128,4): 128-reg budget, guaranteed no local-memory spill.
// Distance arithmetic bit-identical to the R2 kernel (4.7e-8).
// ---------------------------------------------------------------------------
__global__ __launch_bounds__(128, 4) void knn_kernel(const float* __restrict__ pos,
                                                     const float* __restrict__ vel,
                                                     const float* __restrict__ phys,
                                                     const float* __restrict__ refp,
                                                     float* __restrict__ out) {
    __shared__ float cand[4 * 17];               // 4 sorted runs, stride 17
    __shared__ float psum[4][3];

    const int a    = blockIdx.x;                 // global anchor id [0, 2048)
    const int tid  = threadIdx.x;
    const int lane = tid & 31;
    const int wid  = tid >> 5;
    const int obj  = a >> 6;
    const int aidx = g_anchors[a];

    const float* __restrict__ P = pos + (size_t)obj * N_V * 3;
    const float qx = P[aidx * 3 + 0];
    const float qy = P[aidx * 3 + 1];
    const float qz = P[aidx * 3 + 2];
    const float sqq = qx * qx + qy * qy + qz * qz;

    const int base = wid << 9;                   // this warp's 512-point chunk

    // ---- distances for my 16 points (expression identical to R2) ----
    float d[KNN], v[KNN];
#pragma unroll 4
    for (int k = 0; k < KNN; k++) {
        const int j = base + (k << 5) + lane;
        const float x = P[j * 3 + 0], y = P[j * 3 + 1], z = P[j * 3 + 2];
        float dd = (x * x + y * y + z * z + sqq) - 2.0f * (x * qx + y * qy + z * qz);
        if (j == aidx) dd += 1e10f;              // reference's diagonal exclusion
        d[k] = dd;
        v[k] = dd;
    }

    // ---- bitonic sort of the 16 values (ascending), value-only ----
#pragma unroll
    for (int kk = 2; kk <= KNN; kk <<= 1) {
#pragma unroll
        for (int jj = kk >> 1; jj > 0; jj >>= 1) {
#pragma unroll
            for (int i = 0; i < KNN; i++) {
                const int l = i ^ jj;
                if (l > i) {
                    const float va = v[i], vb = v[l];
                    const float lo = fminf(va, vb), hi = fmaxf(va, vb);
                    const bool up = ((i & kk) == 0);
                    v[i] = up ? lo : hi;
                    v[l] = up ? hi : lo;
                }
            }
        }
    }

    // ---- warp merge network: 5 xor-rounds keep-smallest-16 (in place) ----
#pragma unroll
    for (int m = 1; m <= 16; m <<= 1) {
        // half-cleaner vs partner's reversed run; pairwise in-place update
#pragma unroll
        for (int i = 0; i < KNN / 2; i++) {
            const float ph = __shfl_xor_sync(FULL, v[KNN - 1 - i], m);
            const float pl = __shfl_xor_sync(FULL, v[i], m);
            v[i]           = fminf(v[i], ph);
            v[KNN - 1 - i] = fminf(v[KNN - 1 - i], pl);
        }
        // bitonic re-merge of the (bitonic) result, ascending
#pragma unroll
        for (int jj = 8; jj >= 1; jj >>= 1) {
#pragma unroll
            for (int i = 0; i < KNN; i++) {
                if ((i & jj) == 0) {
                    const int l = i | jj;
                    const float lo = fminf(v[i], v[l]);
                    const float hi = fmaxf(v[i], v[l]);
                    v[i] = lo; v[l] = hi;
                }
            }
        }
    }

    // every lane now holds the warp's sorted top-16; lane 0 spills it
    if (lane == 0) {
#pragma unroll
        for (int i = 0; i < KNN; i++) cand[wid * 17 + i] = v[i];
    }
    __syncthreads();

    // ---- final: every warp merges the 4 runs -> T (reuse v registers) ----
    const int L = lane & 3;
#pragma unroll
    for (int i = 0; i < KNN; i++) v[i] = cand[L * 17 + i];

    // round m=1: half-cleaner + full re-merge (next round needs sorted input)
#pragma unroll
    for (int i = 0; i < KNN / 2; i++) {
        const float ph = __shfl_xor_sync(FULL, v[KNN - 1 - i], 1);
        const float pl = __shfl_xor_sync(FULL, v[i], 1);
        v[i]           = fminf(v[i], ph);
        v[KNN - 1 - i] = fminf(v[KNN - 1 - i], pl);
    }
#pragma unroll
    for (int jj = 8; jj >= 1; jj >>= 1) {
#pragma unroll
        for (int i = 0; i < KNN; i++) {
            if ((i & jj) == 0) {
                const int l = i | jj;
                const float lo = fminf(v[i], v[l]);
                const float hi = fmaxf(v[i], v[l]);
                v[i] = lo; v[l] = hi;
            }
        }
    }
    // round m=2: half-cleaner, then T = max of the 16 (no re-sort needed)
#pragma unroll
    for (int i = 0; i < KNN / 2; i++) {
        const float ph = __shfl_xor_sync(FULL, v[KNN - 1 - i], 2);
        const float pl = __shfl_xor_sync(FULL, v[i], 2);
        v[i]           = fminf(v[i], ph);
        v[KNN - 1 - i] = fminf(v[KNN - 1 - i], pl);
    }
    float T = v[0];
#pragma unroll
    for (int i = 1; i < KNN; i++) T = fmaxf(T, v[i]);     // exact 16th smallest

    // ---- accumulate positions of the 16 selected points ----
    float sx = 0.f, sy = 0.f, sz = 0.f;
#pragma unroll 4
    for (int k = 0; k < KNN; k++) {
        if (d[k] <= T) {
            const int j = base + (k << 5) + lane;
            sx += P[j * 3 + 0];
            sy += P[j * 3 + 1];
            sz += P[j * 3 + 2];
        }
    }
#pragma unroll
    for (int off = 16; off; off >>= 1) {
        sx += __shfl_xor_sync(FULL, sx, off);
        sy += __shfl_xor_sync(FULL, sy, off);
        sz += __shfl_xor_sync(FULL, sz, off);
    }
    if (lane == 0) { psum[wid][0] = sx; psum[wid][1] = sy; psum[wid][2] = sz; }
    __syncthreads();

    if (tid == 0) {
        const float nx = psum[0][0] + psum[1][0] + psum[2][0] + psum[3][0];
        const float ny = psum[0][1] + psum[1][1] + psum[2][1] + psum[3][1];
        const float nz = psum[0][2] + psum[1][2] + psum[2][2] + psum[3][2];
        float* __restrict__ o = out + (size_t)a * 12;
        const float inv = 1.0f / 16.0f;
        // anchor_dist: mean(neigh) - p
        o[0] = nx * inv - qx;
        o[1] = ny * inv - qy;
        o[2] = nz * inv - qz;
        // anchor_vel
        const float* __restrict__ V = vel + (size_t)obj * N_V * 3;
        o[3] = V[aidx * 3 + 0];
        o[4] = V[aidx * 3 + 1];
        o[5] = V[aidx * 3 + 2];
        // anchor_rel = pos - ref
        const float* __restrict__ R = refp + (size_t)obj * N_V * 3;
        o[6] = qx - R[aidx * 3 + 0];
        o[7] = qy - R[aidx * 3 + 1];
        o[8] = qz - R[aidx * 3 + 2];
        // physics broadcast
        o[9]  = phys[obj * 3 + 0];
        o[10] = phys[obj * 3 + 1];
        o[11] = phys[obj * 3 + 2];
    }
}

extern "C" void kernel_launch(void* const* d_in, const int* in_sizes, int n_in,
                              void* d_out, int out_size) {
    const float* positions  = (const float*)d_in[0];
    const float* velocities = (const float*)d_in[1];
    const float* physics    = (const float*)d_in[2];
    const float* refpos     = (const float*)d_in[3];
    float* out = (float*)d_out;

    fps_kernel<<<N_OBJS, FPS_THREADS>>>(positions);
    knn_kernel<<<N_OBJS * ANCHORS, 128>>>(positions, velocities, physics, refpos, out);
}